// round 11
// baseline (speedup 1.0000x reference)
#include <cuda_runtime.h>
#include <math.h>
#include <stdint.h>

#define Bn 32
#define Sn 256
#define Hn 4
#define Dn 64
#define Ln 1024
#define Fn 128

// Scratch (device globals are the allowed scratch mechanism)
__device__ float g_ux[Bn*Sn*Hn*Dn];     // mobius_matvec(U, we)   [B,S,H,D]
__device__ float g_wux[Bn*Sn*Hn*Dn];    // W . ux                 [B,S,H,D]
__device__ float g_uxn2[Bn*Sn*Hn];      // ||ux||^2
__device__ float g_uxb[Bn*Sn*Hn];       // ux . b
__device__ float g_enc[Bn*Sn*Hn*Dn];    // RNN states             [B,S,H,D]
__device__ float g_inter[Bn*Ln*Sn];     // sum_h dist             [B,L,S]

__device__ __forceinline__ float warp_sum(float v){
  #pragma unroll
  for (int o = 16; o > 0; o >>= 1) v += __shfl_xor_sync(0xffffffffu, v, o);
  return v;
}

// Fused 3-way butterfly reduction (interleaved chains pipeline the shfl latency).
__device__ __forceinline__ void warp_sum3(float& a, float& b, float& c){
  #pragma unroll
  for (int o = 16; o > 0; o >>= 1){
    a += __shfl_xor_sync(0xffffffffu, a, o);
    b += __shfl_xor_sync(0xffffffffu, b, o);
    c += __shfl_xor_sync(0xffffffffu, c, o);
  }
}

// Warp-collective mobius_matvec (kernelA): Mt transposed [j][i] stride 66.
__device__ __forceinline__ void warp_mmv(const float* Mt, const float* xs, int lane,
                                         float& r0, float& r1, float& sc_out){
  float a0 = 0.f, a1 = 0.f, xn2 = 0.f;
  #pragma unroll
  for (int j = 0; j < 64; j++){
    float xv = xs[j];
    float2 w = *(const float2*)(Mt + j*66 + 2*lane);
    a0  = fmaf(w.x, xv, a0);
    a1  = fmaf(w.y, xv, a1);
    xn2 = fmaf(xv, xv, xn2);
  }
  float mn2 = warp_sum(fmaf(a0, a0, a1*a1));
  float xn = fmaxf(sqrtf(xn2), 1e-15f);
  float mn = fmaxf(sqrtf(mn2), 1e-15f);
  float sc = tanhf(mn / xn * atanhf(fminf(xn, 1.0f - 1e-7f)));
  float inv = sc / mn;
  r0 = a0 * inv;
  r1 = a1 * inv;
  sc_out = sc;
}

// ---------------- Kernel A: gather + ux = mobius_matvec(U, we) + W.ux + ux.b ----
__global__ void kernelA(const int* __restrict__ x,
                        const float* __restrict__ we,
                        const float* __restrict__ U,
                        const float* __restrict__ W,
                        const float* __restrict__ bvec){
  __shared__ float Ut[64*66];
  __shared__ float Wt[64*66];
  __shared__ float xs[64];
  int lane = threadIdx.x;
  int blk = blockIdx.x;
  int chunk = blk & 7;
  int h = (blk >> 3) & 3;
  int b = blk >> 5;
  const float* Ug = U + h*4096;
  const float* Wg = W + h*4096;
  #pragma unroll 4
  for (int i = 0; i < 64; i++){
    Ut[lane*66 + i]      = Ug[i*64 + lane];
    Ut[(lane+32)*66 + i] = Ug[i*64 + lane + 32];
    Wt[lane*66 + i]      = Wg[i*64 + lane];
    Wt[(lane+32)*66 + i] = Wg[i*64 + lane + 32];
  }
  float bb0 = bvec[h*Dn + 2*lane];
  float bb1 = bvec[h*Dn + 2*lane + 1];
  __syncwarp();
  for (int s = chunk*32; s < chunk*32 + 32; s++){
    int xv = x[b*Sn + s];
    float2 wv = *(const float2*)(we + ((size_t)xv*Hn + h)*Dn + 2*lane);
    __syncwarp();
    xs[2*lane]   = wv.x;
    xs[2*lane+1] = wv.y;
    __syncwarp();
    float r0, r1, sc;
    warp_mmv(Ut, xs, lane, r0, r1, sc);
    float uxb = warp_sum(fmaf(r0, bb0, r1*bb1));
    // wux = W . ux  (plain matvec; stage ux into xs)
    __syncwarp();
    xs[2*lane] = r0; xs[2*lane+1] = r1;
    __syncwarp();
    float w0 = 0.f, w1 = 0.f;
    #pragma unroll
    for (int j = 0; j < 64; j++){
      float xj = xs[j];
      float2 w = *(const float2*)(Wt + j*66 + 2*lane);
      w0 = fmaf(w.x, xj, w0);
      w1 = fmaf(w.y, xj, w1);
    }
    int base = ((b*Sn + s)*Hn + h)*Dn;
    *(float2*)(g_ux  + base + 2*lane) = make_float2(r0, r1);
    *(float2*)(g_wux + base + 2*lane) = make_float2(w0, w1);
    if (lane == 0){
      g_uxn2[(b*Sn + s)*Hn + h] = sc*sc;
      g_uxb [(b*Sn + s)*Hn + h] = uxb;
    }
  }
}

// ---------------- Kernel B: hyper-RNN scan via v-space recursion --------------
// State v = W.h carried; the matvec z = W.v overlaps the reduction+scalar chain
// (z is only needed at the very end: v' = a*z + b*wux + g*Wb by linearity).
__global__ void kernelB(const float* __restrict__ W,
                        const float* __restrict__ bvec){
  __shared__ float Ws[64*68];   // row-major W[i][j], row stride 68 (16B aligned)
  __shared__ float vs[64];
  int lane = threadIdx.x;
  int h = blockIdx.x & 3;
  int b = blockIdx.x >> 2;
  const float* Wg = W + h*4096;
  #pragma unroll
  for (int it = 0; it < 32; it++){
    int i = lane + it*32;               // float4 index, 1024 total
    float4 v = ((const float4*)Wg)[i];
    int row = i >> 4, col = (i & 15) * 4;
    *(float4*)&Ws[row*68 + col] = v;
  }
  float bv0 = bvec[h*Dn + 2*lane];
  float bv1 = bvec[h*Dn + 2*lane + 1];
  float bn2 = warp_sum(fmaf(bv0, bv0, bv1*bv1));
  const int r0i = (2*lane)*68, r1i = (2*lane+1)*68;

  // Wb = W . b  (prologue matvec, vs as temp)
  vs[2*lane] = bv0; vs[2*lane+1] = bv1;
  __syncwarp();
  float wb0 = 0.f, wb1 = 0.f;
  #pragma unroll
  for (int j = 0; j < 64; j += 4){
    float4 xv = *(const float4*)&vs[j];
    float4 wa = *(const float4*)&Ws[r0i + j];
    float4 wb = *(const float4*)&Ws[r1i + j];
    wb0 = fmaf(wa.x,xv.x,fmaf(wa.y,xv.y,fmaf(wa.z,xv.z,fmaf(wa.w,xv.w,wb0))));
    wb1 = fmaf(wb.x,xv.x,fmaf(wb.y,xv.y,fmaf(wb.z,xv.z,fmaf(wb.w,xv.w,wb1))));
  }
  __syncwarp();
  vs[2*lane] = 0.f; vs[2*lane+1] = 0.f;
  __syncwarp();

  int ubase = b*Sn*Hn*Dn + h*Dn + 2*lane;   // + t*256
  int nbase = b*Sn*Hn + h;                  // + t*4
  float xn2 = 0.f;                          // ||h||^2 carried analytically
  float v0 = 0.f, v1 = 0.f;                 // v = W.h (lane's 2 components)

  float2 ux  = *(const float2*)(g_ux  + ubase);
  float2 wux = *(const float2*)(g_wux + ubase);
  float uy2 = g_uxn2[nbase];
  float uxb = g_uxb[nbase];

  for (int t = 0; t < Sn; t++){
    float2 ux_n, wux_n; float uy2_n, uxb_n;
    if (t + 1 < Sn){
      ux_n  = *(const float2*)(g_ux  + ubase + (t+1)*(Hn*Dn));
      wux_n = *(const float2*)(g_wux + ubase + (t+1)*(Hn*Dn));
      uy2_n = g_uxn2[nbase + (t+1)*Hn];
      uxb_n = g_uxb [nbase + (t+1)*Hn];
    }
    // reductions on v_t (start the long dependent chain first)
    float mn2 = fmaf(v0, v0, v1*v1);
    float aux = fmaf(v0, ux.x, v1*ux.y);
    float aba = fmaf(v0, bv0, v1*bv1);
    warp_sum3(mn2, aux, aba);

    // z = W . v  (independent issue stream; fills the shfl/MUFU stall shadow)
    float p00=0.f,p01=0.f,p02=0.f,p03=0.f;
    float p10=0.f,p11=0.f,p12=0.f,p13=0.f;
    #pragma unroll
    for (int j = 0; j < 64; j += 4){
      float4 xv = *(const float4*)&vs[j];
      float4 wa = *(const float4*)&Ws[r0i + j];
      float4 wb = *(const float4*)&Ws[r1i + j];
      p00 = fmaf(wa.x, xv.x, p00); p01 = fmaf(wa.y, xv.y, p01);
      p02 = fmaf(wa.z, xv.z, p02); p03 = fmaf(wa.w, xv.w, p03);
      p10 = fmaf(wb.x, xv.x, p10); p11 = fmaf(wb.y, xv.y, p11);
      p12 = fmaf(wb.z, xv.z, p12); p13 = fmaf(wb.w, xv.w, p13);
    }
    float z0 = (p00+p01)+(p02+p03);
    float z1 = (p10+p11)+(p12+p13);

    // scalar mobius algebra (identical on every lane)
    float xn = fmaxf(sqrtf(xn2), 1e-15f);
    float mn = fmaxf(sqrtf(mn2), 1e-15f);
    float xc = fminf(xn, 1.0f - 1e-7f);
    float at = 0.5f * __logf(__fdividef(1.0f + xc, 1.0f - xc));   // atanh
    float r  = __fdividef(mn, xn) * at;
    float em = __expf(-2.0f * r);
    float sc = (1.0f - em) * __fdividef(1.0f, 1.0f + em);          // tanh
    float inv = __fdividef(sc, mn);
    float x2 = sc * sc;
    float xy = inv * aux;                      // wh . ux
    float den = fmaxf(fmaf(x2, uy2, 1.0f + 2.0f*xy), 1e-15f);
    float idn = __fdividef(1.0f, den);
    float cx = (1.0f + 2.0f*xy + uy2) * idn;
    float cy = (1.0f - x2) * idn;
    float cxi = cx * inv;
    float A0 = fmaf(cxi, v0, cy*ux.x);
    float A1 = fmaf(cxi, v1, cy*ux.y);
    float an2 = cx*cx*x2 + 2.0f*cx*cy*xy + cy*cy*uy2;      // ||A||^2
    float ab  = fmaf(cxi, aba, cy*uxb);                    // A . b
    float den2 = fmaxf(fmaf(an2, bn2, 1.0f + 2.0f*ab), 1e-15f);
    float idn2 = __fdividef(1.0f, den2);
    float c2x = (1.0f + 2.0f*ab + bn2) * idn2;
    float c2y = (1.0f - an2) * idn2;
    float n0 = fmaf(c2x, A0, c2y*bv0);          // h_{t+1}
    float n1 = fmaf(c2x, A1, c2y*bv1);
    xn2 = c2x*c2x*an2 + 2.0f*c2x*c2y*ab + c2y*c2y*bn2;     // ||h_{t+1}||^2
    // v_{t+1} = c2x*cxi * z + c2x*cy * (W ux) + c2y * (W b)
    float alpha = c2x * cxi, beta = c2x * cy;
    v0 = fmaf(alpha, z0, fmaf(beta, wux.x, c2y*wb0));
    v1 = fmaf(alpha, z1, fmaf(beta, wux.y, c2y*wb1));
    *(float2*)(g_enc + ubase + t*(Hn*Dn)) = make_float2(n0, n1);
    __syncwarp();
    vs[2*lane] = v0; vs[2*lane+1] = v1;
    __syncwarp();
    ux = ux_n; wux = wux_n; uy2 = uy2_n; uxb = uxb_n;
  }
}

// ---------------- Kernel C: poincare dist to all labels, summed over h ----------------
// R8-measured version: per-h staging, 27KB static smem, 4+ blocks/SM.
// grid = 32 b * 32 l-tiles * 4 s-chunks = 4096 blocks, 256 threads.
// Block tile: 32 labels x 64 s. Thread tile: 4 l x 2 s. Loop hh=0..3, restage.
__global__ void __launch_bounds__(256, 4) kernelC(const float* __restrict__ lab){
  __shared__ float lab_sh[32*68];   // [l][d] for current hh
  __shared__ float enc_sh[64*68];   // [s][d] for current hh
  __shared__ float lb2s[32], ilbs[32];
  __shared__ float as2[64], ias[64];
  int t = threadIdx.x;
  int blk = blockIdx.x;
  int sc = blk & 3;
  int lt = (blk >> 2) & 31;
  int b  = blk >> 7;
  int l0 = lt << 5;
  int s0 = sc << 6;
  int li = t & 7, si = t >> 3;      // 8 l-groups (4 labels), 32 s-groups (2 s)

  float ds[4][2] = {{0.f,0.f},{0.f,0.f},{0.f,0.f},{0.f,0.f}};

  for (int hh = 0; hh < 4; hh++){
    __syncthreads();   // previous iteration's reads complete before restage
    #pragma unroll
    for (int it = 0; it < 2; it++){
      int i = t + it*256;
      int l = i >> 4, dq = (i & 15) << 2;
      float4 v = *(const float4*)(lab + (size_t)(l0 + l)*(Hn*Dn) + hh*Dn + dq);
      *(float4*)&lab_sh[l*68 + dq] = v;
    }
    #pragma unroll
    for (int it = 0; it < 4; it++){
      int i = t + it*256;
      int ss = i >> 4, dq = (i & 15) << 2;
      float4 v = *(const float4*)(g_enc + ((size_t)(b*Sn + s0 + ss)*Hn + hh)*Dn + dq);
      *(float4*)&enc_sh[ss*68 + dq] = v;
    }
    __syncthreads();
    if (t < 32){
      const float* p = &lab_sh[t*68];
      float q0=0.f,q1=0.f,q2=0.f,q3=0.f;
      #pragma unroll
      for (int i = 0; i < 64; i += 4){
        float4 v = *(const float4*)(p + i);
        q0 = fmaf(v.x, v.x, q0); q1 = fmaf(v.y, v.y, q1);
        q2 = fmaf(v.z, v.z, q2); q3 = fmaf(v.w, v.w, q3);
      }
      float s2 = (q0+q1)+(q2+q3);
      lb2s[t] = s2;
      ilbs[t] = __fdividef(1.0f, fmaxf(1.0f - s2, 1e-15f));
    } else if (t < 96){
      int ss = t - 32;
      const float* p = &enc_sh[ss*68];
      float q0=0.f,q1=0.f,q2=0.f,q3=0.f;
      #pragma unroll
      for (int i = 0; i < 64; i += 4){
        float4 v = *(const float4*)(p + i);
        q0 = fmaf(v.x, v.x, q0); q1 = fmaf(v.y, v.y, q1);
        q2 = fmaf(v.z, v.z, q2); q3 = fmaf(v.w, v.w, q3);
      }
      float s2 = (q0+q1)+(q2+q3);
      as2[ss] = s2;
      ias[ss] = __fdividef(1.0f, fmaxf(1.0f - s2, 1e-15f));
    }
    __syncthreads();

    float acc[4][2] = {{0.f,0.f},{0.f,0.f},{0.f,0.f},{0.f,0.f}};
    const float* lp = &lab_sh[li*68];
    const float* ep = &enc_sh[si*68];
    #pragma unroll
    for (int d4 = 0; d4 < 16; d4++){
      float4 la0 = *(const float4*)(lp + 4*d4);
      float4 la1 = *(const float4*)(lp + 8*68  + 4*d4);
      float4 la2 = *(const float4*)(lp + 16*68 + 4*d4);
      float4 la3 = *(const float4*)(lp + 24*68 + 4*d4);
      float4 e0  = *(const float4*)(ep + 4*d4);
      float4 e1  = *(const float4*)(ep + 32*68 + 4*d4);
      acc[0][0] = fmaf(la0.x,e0.x,fmaf(la0.y,e0.y,fmaf(la0.z,e0.z,fmaf(la0.w,e0.w,acc[0][0]))));
      acc[1][0] = fmaf(la1.x,e0.x,fmaf(la1.y,e0.y,fmaf(la1.z,e0.z,fmaf(la1.w,e0.w,acc[1][0]))));
      acc[2][0] = fmaf(la2.x,e0.x,fmaf(la2.y,e0.y,fmaf(la2.z,e0.z,fmaf(la2.w,e0.w,acc[2][0]))));
      acc[3][0] = fmaf(la3.x,e0.x,fmaf(la3.y,e0.y,fmaf(la3.z,e0.z,fmaf(la3.w,e0.w,acc[3][0]))));
      acc[0][1] = fmaf(la0.x,e1.x,fmaf(la0.y,e1.y,fmaf(la0.z,e1.z,fmaf(la0.w,e1.w,acc[0][1]))));
      acc[1][1] = fmaf(la1.x,e1.x,fmaf(la1.y,e1.y,fmaf(la1.z,e1.z,fmaf(la1.w,e1.w,acc[1][1]))));
      acc[2][1] = fmaf(la2.x,e1.x,fmaf(la2.y,e1.y,fmaf(la2.z,e1.z,fmaf(la2.w,e1.w,acc[2][1]))));
      acc[3][1] = fmaf(la3.x,e1.x,fmaf(la3.y,e1.y,fmaf(la3.z,e1.z,fmaf(la3.w,e1.w,acc[3][1]))));
    }
    #pragma unroll
    for (int a = 0; a < 4; a++){
      float lb2 = lb2s[li + a*8];
      float ilb = ilbs[li + a*8];
      #pragma unroll
      for (int q = 0; q < 2; q++){
        float av = as2[si + q*32];
        float ia = ias[si + q*32];
        float c2 = fmaxf(av + lb2 - 2.0f*acc[a][q], 0.0f);
        float tt = fmaxf(2.0f*c2*ia*ilb, 1e-7f);   // = arg - 1
        float prod = fmaf(tt, tt, 2.0f*tt);        // arg^2 - 1
        float sq;
        asm("sqrt.approx.f32 %0, %1;" : "=f"(sq) : "f"(prod));
        ds[a][q] += __logf(1.0f + tt + sq);        // arccosh(arg)
      }
    }
  }
  #pragma unroll
  for (int a = 0; a < 4; a++)
    #pragma unroll
    for (int q = 0; q < 2; q++)
      g_inter[(b*Ln + l0 + li + a*8)*Sn + s0 + si + q*32] = ds[a][q];
}

// ---------------- Kernel D: MLP  out[b,l] = w2 . relu(w1 @ inter + b1) + b2 ----------------
// GEMM [32768 x 256] * [256 x 128], 8x8 thread tile, k-major transposed A tile.
#define ATS 140
#define BTS 132
__global__ void kernelD(const float* __restrict__ w1, const float* __restrict__ b1,
                        const float* __restrict__ w2, const float* __restrict__ b2,
                        float* __restrict__ out){
  __shared__ float At[32*ATS];   // [k][row]
  __shared__ float Bs[32*BTS];   // [k][f]
  int t = threadIdx.x;
  int lane = t & 31;
  int cg = t & 15, rg = t >> 4;
  int r0 = blockIdx.x * 128;
  float acc[8][8];
  #pragma unroll
  for (int i = 0; i < 8; i++)
    #pragma unroll
    for (int j = 0; j < 8; j++) acc[i][j] = 0.f;

  for (int kc = 0; kc < 8; kc++){
    int s0 = kc * 32;
    #pragma unroll
    for (int it = 0; it < 16; it++){
      int row = (t >> 5) + it*8;
      At[lane*ATS + row] = g_inter[(r0 + row)*Sn + s0 + lane];
    }
    #pragma unroll
    for (int it = 0; it < 16; it++){
      int f = (t >> 5) + it*8;
      Bs[lane*BTS + f] = w1[f*Sn + s0 + lane];
    }
    __syncthreads();
    #pragma unroll
    for (int k = 0; k < 32; k++){
      float4 a0 = *(const float4*)(At + k*ATS + rg*8);
      float4 a1 = *(const float4*)(At + k*ATS + rg*8 + 4);
      float4 b0 = *(const float4*)(Bs + k*BTS + cg*8);
      float4 b1q = *(const float4*)(Bs + k*BTS + cg*8 + 4);
      float av[8] = {a0.x,a0.y,a0.z,a0.w,a1.x,a1.y,a1.z,a1.w};
      float bv[8] = {b0.x,b0.y,b0.z,b0.w,b1q.x,b1q.y,b1q.z,b1q.w};
      #pragma unroll
      for (int i = 0; i < 8; i++)
        #pragma unroll
        for (int j = 0; j < 8; j++)
          acc[i][j] = fmaf(av[i], bv[j], acc[i][j]);
    }
    __syncthreads();
  }
  float b1l[8], w2l[8];
  #pragma unroll
  for (int j = 0; j < 8; j++){
    int f = cg*8 + j;
    b1l[j] = b1[f];
    w2l[j] = w2[f];
  }
  float p[8];
  #pragma unroll
  for (int i = 0; i < 8; i++){
    float s = 0.f;
    #pragma unroll
    for (int j = 0; j < 8; j++)
      s = fmaf(fmaxf(acc[i][j] + b1l[j], 0.f), w2l[j], s);
    p[i] = s;
  }
  #pragma unroll
  for (int o = 1; o < 16; o <<= 1){
    #pragma unroll
    for (int i = 0; i < 8; i++) p[i] += __shfl_xor_sync(0xffffffffu, p[i], o);
  }
  if (cg == 0){
    float bb = b2[0];
    #pragma unroll
    for (int i = 0; i < 8; i++) out[r0 + rg*8 + i] = p[i] + bb;
  }
}

extern "C" void kernel_launch(void* const* d_in, const int* in_sizes, int n_in,
                              void* d_out, int out_size){
  const int*   x   = (const int*)  d_in[0];
  const float* we  = (const float*)d_in[1];
  const float* lab = (const float*)d_in[2];
  const float* W   = (const float*)d_in[3];
  const float* U   = (const float*)d_in[4];
  const float* bv  = (const float*)d_in[5];
  const float* w1  = (const float*)d_in[6];
  const float* b1  = (const float*)d_in[7];
  const float* w2  = (const float*)d_in[8];
  const float* b2  = (const float*)d_in[9];
  float* out = (float*)d_out;

  kernelA<<<1024, 32>>>(x, we, U, W, bv);
  kernelB<<<128, 32>>>(W, bv);
  kernelC<<<4096, 256>>>(lab);
  kernelD<<<256, 256>>>(w1, b1, w2, b2, out);
}

// round 13
// speedup vs baseline: 1.0983x; 1.0983x over previous
#include <cuda_runtime.h>
#include <math.h>
#include <stdint.h>

#define Bn 32
#define Sn 256
#define Hn 4
#define Dn 64
#define Ln 1024
#define Fn 128

// Scratch (device globals are the allowed scratch mechanism)
__device__ float g_ux[Bn*Sn*Hn*Dn];     // mobius_matvec(U, we)  [B,S,H,D]
__device__ float g_uxn2[Bn*Sn*Hn];      // ||ux||^2
__device__ float g_enc[Bn*Sn*Hn*Dn];    // RNN states            [B,S,H,D]
__device__ float g_inter[Bn*Ln*Sn];     // sum_h dist            [B,L,S]

__device__ __forceinline__ float warp_sum(float v){
  #pragma unroll
  for (int o = 16; o > 0; o >>= 1) v += __shfl_xor_sync(0xffffffffu, v, o);
  return v;
}

// Fused 4-way butterfly reduction: all four scalars reduced in one pass.
__device__ __forceinline__ void warp_sum4(float& a, float& b, float& c, float& d){
  #pragma unroll
  for (int o = 16; o > 0; o >>= 1){
    a += __shfl_xor_sync(0xffffffffu, a, o);
    b += __shfl_xor_sync(0xffffffffu, b, o);
    c += __shfl_xor_sync(0xffffffffu, c, o);
    d += __shfl_xor_sync(0xffffffffu, d, o);
  }
}

// Warp-collective mobius_matvec (kernelA): Wt transposed [j][i] stride 66.
__device__ __forceinline__ void warp_mmv(const float* Wt, const float* xs, int lane,
                                         float& r0, float& r1, float& sc_out){
  float a0 = 0.f, a1 = 0.f, xn2 = 0.f;
  #pragma unroll
  for (int j = 0; j < 64; j++){
    float xv = xs[j];
    float2 w = *(const float2*)(Wt + j*66 + 2*lane);
    a0  = fmaf(w.x, xv, a0);
    a1  = fmaf(w.y, xv, a1);
    xn2 = fmaf(xv, xv, xn2);
  }
  float mn2 = warp_sum(fmaf(a0, a0, a1*a1));
  float xn = fmaxf(sqrtf(xn2), 1e-15f);
  float mn = fmaxf(sqrtf(mn2), 1e-15f);
  float sc = tanhf(mn / xn * atanhf(fminf(xn, 1.0f - 1e-7f)));
  float inv = sc / mn;
  r0 = a0 * inv;
  r1 = a1 * inv;
  sc_out = sc;
}

// ---------------- Kernel A: gather + ux = mobius_matvec(U, we) ----------------
__global__ void kernelA(const int* __restrict__ x,
                        const float* __restrict__ we,
                        const float* __restrict__ U){
  __shared__ float Ut[64*66];
  __shared__ float xs[64];
  int lane = threadIdx.x;
  int blk = blockIdx.x;
  int chunk = blk & 7;
  int h = (blk >> 3) & 3;
  int b = blk >> 5;
  const float* Ug = U + h*64*64;
  #pragma unroll 4
  for (int i = 0; i < 64; i++){
    Ut[lane*66 + i]      = Ug[i*64 + lane];
    Ut[(lane+32)*66 + i] = Ug[i*64 + lane + 32];
  }
  __syncwarp();
  for (int s = chunk*32; s < chunk*32 + 32; s++){
    int xv = x[b*Sn + s];
    float2 wv = *(const float2*)(we + ((size_t)xv*Hn + h)*Dn + 2*lane);
    __syncwarp();
    xs[2*lane]   = wv.x;
    xs[2*lane+1] = wv.y;
    __syncwarp();
    float r0, r1, sc;
    warp_mmv(Ut, xs, lane, r0, r1, sc);
    int base = ((b*Sn + s)*Hn + h)*Dn;
    *(float2*)(g_ux + base + 2*lane) = make_float2(r0, r1);
    if (lane == 0) g_uxn2[(b*Sn + s)*Hn + h] = sc*sc;
  }
}

// ---------------- Filler no-op kernels (profiler launch-index steering) -------
__global__ void kernelNop1(){}
__global__ void kernelNop2(){}

// ---------------- Kernel B: sequential hyper-RNN scan (1 warp / chain) --------
// Single fused 4-way reduction per step + closed-form scalar algebra + fast math.
// Scalar chain micro-opt: em = exp(cc*log(q)) fuses tanh(c*atanh(x)); one
// shared reciprocal replaces the sc/mn divide.
__global__ void kernelB(const float* __restrict__ W,
                        const float* __restrict__ bvec){
  __shared__ float Ws[64*68];   // row-major W[i][j], row stride 68 (16B aligned)
  __shared__ float hs[64];
  int lane = threadIdx.x;
  int h = blockIdx.x & 3;
  int b = blockIdx.x >> 2;
  const float* Wg = W + h*4096;
  #pragma unroll
  for (int it = 0; it < 32; it++){
    int i = lane + it*32;               // float4 index, 1024 total
    float4 v = ((const float4*)Wg)[i];
    int row = i >> 4, col = (i & 15) * 4;
    *(float4*)&Ws[row*68 + col] = v;
  }
  float bv0 = bvec[h*Dn + 2*lane];
  float bv1 = bvec[h*Dn + 2*lane + 1];
  float bn2 = warp_sum(fmaf(bv0, bv0, bv1*bv1));
  hs[2*lane] = 0.f; hs[2*lane+1] = 0.f;
  __syncwarp();

  int ubase = b*Sn*Hn*Dn + h*Dn + 2*lane;   // + t*256
  int nbase = b*Sn*Hn + h;                  // + t*4
  float xn2 = 0.f;                          // ||h||^2 carried analytically
  const int r0i = (2*lane)*68, r1i = (2*lane+1)*68;

  float2 ux = *(const float2*)(g_ux + ubase);
  float uy2 = g_uxn2[nbase];

  for (int t = 0; t < Sn; t++){
    float2 ux_n; float uy2_n;
    if (t + 1 < Sn){
      ux_n  = *(const float2*)(g_ux + ubase + (t+1)*(Hn*Dn));
      uy2_n = g_uxn2[nbase + (t+1)*Hn];
    }
    // matvec a = W h : rows 2*lane, 2*lane+1; 4 partial accumulators each
    float p00=0.f,p01=0.f,p02=0.f,p03=0.f;
    float p10=0.f,p11=0.f,p12=0.f,p13=0.f;
    #pragma unroll
    for (int j = 0; j < 64; j += 4){
      float4 xv = *(const float4*)&hs[j];
      float4 wa = *(const float4*)&Ws[r0i + j];
      float4 wb = *(const float4*)&Ws[r1i + j];
      p00 = fmaf(wa.x, xv.x, p00); p01 = fmaf(wa.y, xv.y, p01);
      p02 = fmaf(wa.z, xv.z, p02); p03 = fmaf(wa.w, xv.w, p03);
      p10 = fmaf(wb.x, xv.x, p10); p11 = fmaf(wb.y, xv.y, p11);
      p12 = fmaf(wb.z, xv.z, p12); p13 = fmaf(wb.w, xv.w, p13);
    }
    float a0 = (p00+p01)+(p02+p03);
    float a1 = (p10+p11)+(p12+p13);
    // one fused 4-way reduction pass: |a|^2, a.ux, a.b, ux.b
    float mn2 = fmaf(a0, a0, a1*a1);
    float aux = fmaf(a0, ux.x, a1*ux.y);
    float aba = fmaf(a0, bv0, a1*bv1);
    float uxb = fmaf(ux.x, bv0, ux.y*bv1);
    warp_sum4(mn2, aux, aba, uxb);
    // scalar mobius algebra (identical on every lane)
    float xn = fmaxf(sqrtf(xn2), 1e-15f);
    float mn = fmaxf(sqrtf(mn2), 1e-15f);
    float xc = fminf(xn, 1.0f - 1e-7f);
    float q  = __fdividef(1.0f - xc, 1.0f + xc);
    float cc = __fdividef(mn, xn);
    float em = __expf(cc * __logf(q));         // ((1-xc)/(1+xc))^cc = exp(-2*cc*atanh(xc))
    float rm = __fdividef(1.0f, (1.0f + em) * mn);
    float inv = (1.0f - em) * rm;              // sc / mn
    float sc  = inv * mn;                      // tanh(cc * atanh(xc))
    float x2 = sc * sc;
    float xy = inv * aux;                      // wh . ux
    float den = fmaxf(fmaf(x2, uy2, 1.0f + 2.0f*xy), 1e-15f);
    float idn = __fdividef(1.0f, den);
    float cx = (1.0f + 2.0f*xy + uy2) * idn;
    float cy = (1.0f - x2) * idn;
    float cxi = cx * inv;
    float A0 = fmaf(cxi, a0, cy*ux.x);
    float A1 = fmaf(cxi, a1, cy*ux.y);
    float an2 = cx*cx*x2 + 2.0f*cx*cy*xy + cy*cy*uy2;      // ||A||^2
    float ab  = fmaf(cxi, aba, cy*uxb);                    // A . b
    float den2 = fmaxf(fmaf(an2, bn2, 1.0f + 2.0f*ab), 1e-15f);
    float idn2 = __fdividef(1.0f, den2);
    float c2x = (1.0f + 2.0f*ab + bn2) * idn2;
    float c2y = (1.0f - an2) * idn2;
    float n0 = fmaf(c2x, A0, c2y*bv0);
    float n1 = fmaf(c2x, A1, c2y*bv1);
    xn2 = c2x*c2x*an2 + 2.0f*c2x*c2y*ab + c2y*c2y*bn2;     // ||h_new||^2
    __syncwarp();
    hs[2*lane] = n0; hs[2*lane+1] = n1;
    __syncwarp();
    *(float2*)(g_enc + ubase + t*(Hn*Dn)) = make_float2(n0, n1);
    ux = ux_n; uy2 = uy2_n;
  }
}

// ---------------- Kernel C: poincare dist to all labels, summed over h ----------------
// R8-measured version: per-h staging, 27KB static smem, 4+ blocks/SM.
// grid = 32 b * 32 l-tiles * 4 s-chunks = 4096 blocks, 256 threads.
// Block tile: 32 labels x 64 s. Thread tile: 4 l x 2 s. Loop hh=0..3, restage.
__global__ void __launch_bounds__(256, 4) kernelC(const float* __restrict__ lab){
  __shared__ float lab_sh[32*68];   // [l][d] for current hh
  __shared__ float enc_sh[64*68];   // [s][d] for current hh
  __shared__ float lb2s[32], ilbs[32];
  __shared__ float as2[64], ias[64];
  int t = threadIdx.x;
  int blk = blockIdx.x;
  int sc = blk & 3;
  int lt = (blk >> 2) & 31;
  int b  = blk >> 7;
  int l0 = lt << 5;
  int s0 = sc << 6;
  int li = t & 7, si = t >> 3;      // 8 l-groups (4 labels), 32 s-groups (2 s)

  float ds[4][2] = {{0.f,0.f},{0.f,0.f},{0.f,0.f},{0.f,0.f}};

  for (int hh = 0; hh < 4; hh++){
    __syncthreads();   // previous iteration's reads complete before restage
    #pragma unroll
    for (int it = 0; it < 2; it++){
      int i = t + it*256;
      int l = i >> 4, dq = (i & 15) << 2;
      float4 v = *(const float4*)(lab + (size_t)(l0 + l)*(Hn*Dn) + hh*Dn + dq);
      *(float4*)&lab_sh[l*68 + dq] = v;
    }
    #pragma unroll
    for (int it = 0; it < 4; it++){
      int i = t + it*256;
      int ss = i >> 4, dq = (i & 15) << 2;
      float4 v = *(const float4*)(g_enc + ((size_t)(b*Sn + s0 + ss)*Hn + hh)*Dn + dq);
      *(float4*)&enc_sh[ss*68 + dq] = v;
    }
    __syncthreads();
    if (t < 32){
      const float* p = &lab_sh[t*68];
      float q0=0.f,q1=0.f,q2=0.f,q3=0.f;
      #pragma unroll
      for (int i = 0; i < 64; i += 4){
        float4 v = *(const float4*)(p + i);
        q0 = fmaf(v.x, v.x, q0); q1 = fmaf(v.y, v.y, q1);
        q2 = fmaf(v.z, v.z, q2); q3 = fmaf(v.w, v.w, q3);
      }
      float s2 = (q0+q1)+(q2+q3);
      lb2s[t] = s2;
      ilbs[t] = __fdividef(1.0f, fmaxf(1.0f - s2, 1e-15f));
    } else if (t < 96){
      int ss = t - 32;
      const float* p = &enc_sh[ss*68];
      float q0=0.f,q1=0.f,q2=0.f,q3=0.f;
      #pragma unroll
      for (int i = 0; i < 64; i += 4){
        float4 v = *(const float4*)(p + i);
        q0 = fmaf(v.x, v.x, q0); q1 = fmaf(v.y, v.y, q1);
        q2 = fmaf(v.z, v.z, q2); q3 = fmaf(v.w, v.w, q3);
      }
      float s2 = (q0+q1)+(q2+q3);
      as2[ss] = s2;
      ias[ss] = __fdividef(1.0f, fmaxf(1.0f - s2, 1e-15f));
    }
    __syncthreads();

    float acc[4][2] = {{0.f,0.f},{0.f,0.f},{0.f,0.f},{0.f,0.f}};
    const float* lp = &lab_sh[li*68];
    const float* ep = &enc_sh[si*68];
    #pragma unroll
    for (int d4 = 0; d4 < 16; d4++){
      float4 la0 = *(const float4*)(lp + 4*d4);
      float4 la1 = *(const float4*)(lp + 8*68  + 4*d4);
      float4 la2 = *(const float4*)(lp + 16*68 + 4*d4);
      float4 la3 = *(const float4*)(lp + 24*68 + 4*d4);
      float4 e0  = *(const float4*)(ep + 4*d4);
      float4 e1  = *(const float4*)(ep + 32*68 + 4*d4);
      acc[0][0] = fmaf(la0.x,e0.x,fmaf(la0.y,e0.y,fmaf(la0.z,e0.z,fmaf(la0.w,e0.w,acc[0][0]))));
      acc[1][0] = fmaf(la1.x,e0.x,fmaf(la1.y,e0.y,fmaf(la1.z,e0.z,fmaf(la1.w,e0.w,acc[1][0]))));
      acc[2][0] = fmaf(la2.x,e0.x,fmaf(la2.y,e0.y,fmaf(la2.z,e0.z,fmaf(la2.w,e0.w,acc[2][0]))));
      acc[3][0] = fmaf(la3.x,e0.x,fmaf(la3.y,e0.y,fmaf(la3.z,e0.z,fmaf(la3.w,e0.w,acc[3][0]))));
      acc[0][1] = fmaf(la0.x,e1.x,fmaf(la0.y,e1.y,fmaf(la0.z,e1.z,fmaf(la0.w,e1.w,acc[0][1]))));
      acc[1][1] = fmaf(la1.x,e1.x,fmaf(la1.y,e1.y,fmaf(la1.z,e1.z,fmaf(la1.w,e1.w,acc[1][1]))));
      acc[2][1] = fmaf(la2.x,e1.x,fmaf(la2.y,e1.y,fmaf(la2.z,e1.z,fmaf(la2.w,e1.w,acc[2][1]))));
      acc[3][1] = fmaf(la3.x,e1.x,fmaf(la3.y,e1.y,fmaf(la3.z,e1.z,fmaf(la3.w,e1.w,acc[3][1]))));
    }
    #pragma unroll
    for (int a = 0; a < 4; a++){
      float lb2 = lb2s[li + a*8];
      float ilb = ilbs[li + a*8];
      #pragma unroll
      for (int q = 0; q < 2; q++){
        float av = as2[si + q*32];
        float ia = ias[si + q*32];
        float c2 = fmaxf(av + lb2 - 2.0f*acc[a][q], 0.0f);
        float tt = fmaxf(2.0f*c2*ia*ilb, 1e-7f);   // = arg - 1
        float prod = fmaf(tt, tt, 2.0f*tt);        // arg^2 - 1
        float sq;
        asm("sqrt.approx.f32 %0, %1;" : "=f"(sq) : "f"(prod));
        ds[a][q] += __logf(1.0f + tt + sq);        // arccosh(arg)
      }
    }
  }
  #pragma unroll
  for (int a = 0; a < 4; a++)
    #pragma unroll
    for (int q = 0; q < 2; q++)
      g_inter[(b*Ln + l0 + li + a*8)*Sn + s0 + si + q*32] = ds[a][q];
}

// ---------------- Kernel D: MLP  out[b,l] = w2 . relu(w1 @ inter + b1) + b2 ----------------
// GEMM [32768 x 256] * [256 x 128], 8x8 thread tile, k-major transposed A tile.
#define ATS 140
#define BTS 132
__global__ void kernelD(const float* __restrict__ w1, const float* __restrict__ b1,
                        const float* __restrict__ w2, const float* __restrict__ b2,
                        float* __restrict__ out){
  __shared__ float At[32*ATS];   // [k][row]
  __shared__ float Bs[32*BTS];   // [k][f]
  int t = threadIdx.x;
  int lane = t & 31;
  int cg = t & 15, rg = t >> 4;
  int r0 = blockIdx.x * 128;
  float acc[8][8];
  #pragma unroll
  for (int i = 0; i < 8; i++)
    #pragma unroll
    for (int j = 0; j < 8; j++) acc[i][j] = 0.f;

  for (int kc = 0; kc < 8; kc++){
    int s0 = kc * 32;
    #pragma unroll
    for (int it = 0; it < 16; it++){
      int row = (t >> 5) + it*8;
      At[lane*ATS + row] = g_inter[(r0 + row)*Sn + s0 + lane];
    }
    #pragma unroll
    for (int it = 0; it < 16; it++){
      int f = (t >> 5) + it*8;
      Bs[lane*BTS + f] = w1[f*Sn + s0 + lane];
    }
    __syncthreads();
    #pragma unroll
    for (int k = 0; k < 32; k++){
      float4 a0 = *(const float4*)(At + k*ATS + rg*8);
      float4 a1 = *(const float4*)(At + k*ATS + rg*8 + 4);
      float4 b0 = *(const float4*)(Bs + k*BTS + cg*8);
      float4 b1q = *(const float4*)(Bs + k*BTS + cg*8 + 4);
      float av[8] = {a0.x,a0.y,a0.z,a0.w,a1.x,a1.y,a1.z,a1.w};
      float bv[8] = {b0.x,b0.y,b0.z,b0.w,b1q.x,b1q.y,b1q.z,b1q.w};
      #pragma unroll
      for (int i = 0; i < 8; i++)
        #pragma unroll
        for (int j = 0; j < 8; j++)
          acc[i][j] = fmaf(av[i], bv[j], acc[i][j]);
    }
    __syncthreads();
  }
  float b1l[8], w2l[8];
  #pragma unroll
  for (int j = 0; j < 8; j++){
    int f = cg*8 + j;
    b1l[j] = b1[f];
    w2l[j] = w2[f];
  }
  float p[8];
  #pragma unroll
  for (int i = 0; i < 8; i++){
    float s = 0.f;
    #pragma unroll
    for (int j = 0; j < 8; j++)
      s = fmaf(fmaxf(acc[i][j] + b1l[j], 0.f), w2l[j], s);
    p[i] = s;
  }
  #pragma unroll
  for (int o = 1; o < 16; o <<= 1){
    #pragma unroll
    for (int i = 0; i < 8; i++) p[i] += __shfl_xor_sync(0xffffffffu, p[i], o);
  }
  if (cg == 0){
    float bb = b2[0];
    #pragma unroll
    for (int i = 0; i < 8; i++) out[r0 + rg*8 + i] = p[i] + bb;
  }
}

extern "C" void kernel_launch(void* const* d_in, const int* in_sizes, int n_in,
                              void* d_out, int out_size){
  const int*   x   = (const int*)  d_in[0];
  const float* we  = (const float*)d_in[1];
  const float* lab = (const float*)d_in[2];
  const float* W   = (const float*)d_in[3];
  const float* U   = (const float*)d_in[4];
  const float* bv  = (const float*)d_in[5];
  const float* w1  = (const float*)d_in[6];
  const float* b1  = (const float*)d_in[7];
  const float* w2  = (const float*)d_in[8];
  const float* b2  = (const float*)d_in[9];
  float* out = (float*)d_out;

  kernelA<<<1024, 32>>>(x, we, U);
  kernelNop1<<<1, 32>>>();
  kernelNop2<<<1, 32>>>();
  kernelB<<<128, 32>>>(W, bv);       // 4th launch -> profiler target
  kernelC<<<4096, 256>>>(lab);
  kernelD<<<256, 256>>>(w1, b1, w2, b2, out);
}

// round 14
// speedup vs baseline: 1.2473x; 1.1357x over previous
#include <cuda_runtime.h>
#include <math.h>
#include <stdint.h>

#define Bn 32
#define Sn 256
#define Hn 4
#define Dn 64
#define Ln 1024
#define Fn 128

// Scratch (device globals are the allowed scratch mechanism)
__device__ float g_ux[Bn*Sn*Hn*Dn];     // mobius_matvec(U, we)  [B,S,H,D]
__device__ float g_uxn2[Bn*Sn*Hn];      // ||ux||^2
__device__ float g_uxb[Bn*Sn*Hn];       // ux . b (precomputed)
__device__ float g_enc[Bn*Sn*Hn*Dn];    // RNN states            [B,S,H,D]
__device__ float g_inter[Bn*Ln*Sn];     // sum_h dist            [B,L,S]

__device__ __forceinline__ float warp_sum(float v){
  #pragma unroll
  for (int o = 16; o > 0; o >>= 1) v += __shfl_xor_sync(0xffffffffu, v, o);
  return v;
}

// Fused 3-way butterfly reduction (chains pipeline the shfl latency).
__device__ __forceinline__ void warp_sum3(float& a, float& b, float& c){
  #pragma unroll
  for (int o = 16; o > 0; o >>= 1){
    a += __shfl_xor_sync(0xffffffffu, a, o);
    b += __shfl_xor_sync(0xffffffffu, b, o);
    c += __shfl_xor_sync(0xffffffffu, c, o);
  }
}

// Warp-collective mobius_matvec (kernelA): Wt transposed [j][i] stride 66.
__device__ __forceinline__ void warp_mmv(const float* Wt, const float* xs, int lane,
                                         float& r0, float& r1, float& sc_out){
  float a0 = 0.f, a1 = 0.f, xn2 = 0.f;
  #pragma unroll
  for (int j = 0; j < 64; j++){
    float xv = xs[j];
    float2 w = *(const float2*)(Wt + j*66 + 2*lane);
    a0  = fmaf(w.x, xv, a0);
    a1  = fmaf(w.y, xv, a1);
    xn2 = fmaf(xv, xv, xn2);
  }
  float mn2 = warp_sum(fmaf(a0, a0, a1*a1));
  float xn = fmaxf(sqrtf(xn2), 1e-15f);
  float mn = fmaxf(sqrtf(mn2), 1e-15f);
  float sc = tanhf(mn / xn * atanhf(fminf(xn, 1.0f - 1e-7f)));
  float inv = sc / mn;
  r0 = a0 * inv;
  r1 = a1 * inv;
  sc_out = sc;
}

// ---------------- Kernel A: gather + ux = mobius_matvec(U, we) + ux.b ---------
__global__ void kernelA(const int* __restrict__ x,
                        const float* __restrict__ we,
                        const float* __restrict__ U,
                        const float* __restrict__ bvec){
  __shared__ float Ut[64*66];
  __shared__ float xs[64];
  int lane = threadIdx.x;
  int blk = blockIdx.x;
  int chunk = blk & 7;
  int h = (blk >> 3) & 3;
  int b = blk >> 5;
  const float* Ug = U + h*64*64;
  #pragma unroll 4
  for (int i = 0; i < 64; i++){
    Ut[lane*66 + i]      = Ug[i*64 + lane];
    Ut[(lane+32)*66 + i] = Ug[i*64 + lane + 32];
  }
  float bb0 = bvec[h*Dn + 2*lane];
  float bb1 = bvec[h*Dn + 2*lane + 1];
  __syncwarp();
  for (int s = chunk*32; s < chunk*32 + 32; s++){
    int xv = x[b*Sn + s];
    float2 wv = *(const float2*)(we + ((size_t)xv*Hn + h)*Dn + 2*lane);
    __syncwarp();
    xs[2*lane]   = wv.x;
    xs[2*lane+1] = wv.y;
    __syncwarp();
    float r0, r1, sc;
    warp_mmv(Ut, xs, lane, r0, r1, sc);
    float uxb = warp_sum(fmaf(r0, bb0, r1*bb1));
    int base = ((b*Sn + s)*Hn + h)*Dn;
    *(float2*)(g_ux + base + 2*lane) = make_float2(r0, r1);
    if (lane == 0){
      g_uxn2[(b*Sn + s)*Hn + h] = sc*sc;
      g_uxb [(b*Sn + s)*Hn + h] = uxb;
    }
  }
}

// ---------------- Filler no-op kernels (profiler launch-index steering) -------
__global__ void kernelNop1(){}
__global__ void kernelNop2(){}

// ---------------- Kernel B: sequential hyper-RNN scan (1 warp / chain) --------
// ALL-REGISTER version: W rows in registers (1 warp/SM -> regs are free),
// h distributed as float2/lane, matvec via shfl broadcast. No smem, no
// syncwarp, no STS/LDS in the loop. 3-way fused butterfly (ux.b precomputed).
__global__ void __launch_bounds__(32, 1) kernelB(const float* __restrict__ W,
                                                 const float* __restrict__ bvec){
  int lane = threadIdx.x;
  int h = blockIdx.x & 3;
  int b = blockIdx.x >> 2;
  const float* Wg = W + h*4096;

  // Prologue: this lane's two W rows into registers (statically indexed).
  float w0[64], w1[64];
  #pragma unroll
  for (int j4 = 0; j4 < 16; j4++){
    float4 v0 = *(const float4*)(Wg + (2*lane)*64   + 4*j4);
    float4 v1 = *(const float4*)(Wg + (2*lane+1)*64 + 4*j4);
    w0[4*j4+0]=v0.x; w0[4*j4+1]=v0.y; w0[4*j4+2]=v0.z; w0[4*j4+3]=v0.w;
    w1[4*j4+0]=v1.x; w1[4*j4+1]=v1.y; w1[4*j4+2]=v1.z; w1[4*j4+3]=v1.w;
  }
  float bv0 = bvec[h*Dn + 2*lane];
  float bv1 = bvec[h*Dn + 2*lane + 1];
  float bn2 = warp_sum(fmaf(bv0, bv0, bv1*bv1));

  int ubase = b*Sn*Hn*Dn + h*Dn + 2*lane;   // + t*256
  int nbase = b*Sn*Hn + h;                  // + t*4
  float xn2 = 0.f;                          // ||h||^2 carried analytically
  float hx = 0.f, hy = 0.f;                 // h[2*lane], h[2*lane+1]

  float2 ux = *(const float2*)(g_ux + ubase);
  float uy2 = g_uxn2[nbase];
  float uxb = g_uxb[nbase];

  for (int t = 0; t < Sn; t++){
    float2 ux_n; float uy2_n, uxb_n;
    if (t + 1 < Sn){
      ux_n  = *(const float2*)(g_ux + ubase + (t+1)*(Hn*Dn));
      uy2_n = g_uxn2[nbase + (t+1)*Hn];
      uxb_n = g_uxb [nbase + (t+1)*Hn];
    }
    // matvec a = W h via shfl broadcast: 64 shfl + 128 FMA, all independent.
    float a00=0.f, a01=0.f, a10=0.f, a11=0.f;
    #pragma unroll
    for (int j = 0; j < 32; j++){
      float sx = __shfl_sync(0xffffffffu, hx, j);
      float sy = __shfl_sync(0xffffffffu, hy, j);
      a00 = fmaf(w0[2*j],   sx, a00);
      a01 = fmaf(w0[2*j+1], sy, a01);
      a10 = fmaf(w1[2*j],   sx, a10);
      a11 = fmaf(w1[2*j+1], sy, a11);
    }
    float a0 = a00 + a01;
    float a1 = a10 + a11;
    // one fused 3-way reduction pass: |a|^2, a.ux, a.b  (ux.b precomputed)
    float mn2 = fmaf(a0, a0, a1*a1);
    float aux = fmaf(a0, ux.x, a1*ux.y);
    float aba = fmaf(a0, bv0, a1*bv1);
    warp_sum3(mn2, aux, aba);
    // scalar mobius algebra (identical on every lane)
    float xn = fmaxf(sqrtf(xn2), 1e-15f);
    float mn = fmaxf(sqrtf(mn2), 1e-15f);
    float xc = fminf(xn, 1.0f - 1e-7f);
    float q  = __fdividef(1.0f - xc, 1.0f + xc);
    float cc = __fdividef(mn, xn);
    float em = __expf(cc * __logf(q));         // ((1-xc)/(1+xc))^cc = exp(-2*cc*atanh(xc))
    float rm = __fdividef(1.0f, (1.0f + em) * mn);
    float inv = (1.0f - em) * rm;              // sc / mn
    float sc  = inv * mn;                      // tanh(cc * atanh(xc))
    float x2 = sc * sc;
    float xy = inv * aux;                      // wh . ux
    float den = fmaxf(fmaf(x2, uy2, 1.0f + 2.0f*xy), 1e-15f);
    float idn = __fdividef(1.0f, den);
    float cx = (1.0f + 2.0f*xy + uy2) * idn;
    float cy = (1.0f - x2) * idn;
    float cxi = cx * inv;
    float A0 = fmaf(cxi, a0, cy*ux.x);
    float A1 = fmaf(cxi, a1, cy*ux.y);
    float an2 = cx*cx*x2 + 2.0f*cx*cy*xy + cy*cy*uy2;      // ||A||^2
    float ab  = fmaf(cxi, aba, cy*uxb);                    // A . b
    float den2 = fmaxf(fmaf(an2, bn2, 1.0f + 2.0f*ab), 1e-15f);
    float idn2 = __fdividef(1.0f, den2);
    float c2x = (1.0f + 2.0f*ab + bn2) * idn2;
    float c2y = (1.0f - an2) * idn2;
    hx = fmaf(c2x, A0, c2y*bv0);               // h_{t+1}
    hy = fmaf(c2x, A1, c2y*bv1);
    xn2 = c2x*c2x*an2 + 2.0f*c2x*c2y*ab + c2y*c2y*bn2;     // ||h_{t+1}||^2
    *(float2*)(g_enc + ubase + t*(Hn*Dn)) = make_float2(hx, hy);
    ux = ux_n; uy2 = uy2_n; uxb = uxb_n;
  }
}

// ---------------- Kernel C: poincare dist to all labels, summed over h ----------------
// R8-measured version: per-h staging, 27KB static smem, 4+ blocks/SM.
// grid = 32 b * 32 l-tiles * 4 s-chunks = 4096 blocks, 256 threads.
// Block tile: 32 labels x 64 s. Thread tile: 4 l x 2 s. Loop hh=0..3, restage.
__global__ void __launch_bounds__(256, 4) kernelC(const float* __restrict__ lab){
  __shared__ float lab_sh[32*68];   // [l][d] for current hh
  __shared__ float enc_sh[64*68];   // [s][d] for current hh
  __shared__ float lb2s[32], ilbs[32];
  __shared__ float as2[64], ias[64];
  int t = threadIdx.x;
  int blk = blockIdx.x;
  int sc = blk & 3;
  int lt = (blk >> 2) & 31;
  int b  = blk >> 7;
  int l0 = lt << 5;
  int s0 = sc << 6;
  int li = t & 7, si = t >> 3;      // 8 l-groups (4 labels), 32 s-groups (2 s)

  float ds[4][2] = {{0.f,0.f},{0.f,0.f},{0.f,0.f},{0.f,0.f}};

  for (int hh = 0; hh < 4; hh++){
    __syncthreads();   // previous iteration's reads complete before restage
    #pragma unroll
    for (int it = 0; it < 2; it++){
      int i = t + it*256;
      int l = i >> 4, dq = (i & 15) << 2;
      float4 v = *(const float4*)(lab + (size_t)(l0 + l)*(Hn*Dn) + hh*Dn + dq);
      *(float4*)&lab_sh[l*68 + dq] = v;
    }
    #pragma unroll
    for (int it = 0; it < 4; it++){
      int i = t + it*256;
      int ss = i >> 4, dq = (i & 15) << 2;
      float4 v = *(const float4*)(g_enc + ((size_t)(b*Sn + s0 + ss)*Hn + hh)*Dn + dq);
      *(float4*)&enc_sh[ss*68 + dq] = v;
    }
    __syncthreads();
    if (t < 32){
      const float* p = &lab_sh[t*68];
      float q0=0.f,q1=0.f,q2=0.f,q3=0.f;
      #pragma unroll
      for (int i = 0; i < 64; i += 4){
        float4 v = *(const float4*)(p + i);
        q0 = fmaf(v.x, v.x, q0); q1 = fmaf(v.y, v.y, q1);
        q2 = fmaf(v.z, v.z, q2); q3 = fmaf(v.w, v.w, q3);
      }
      float s2 = (q0+q1)+(q2+q3);
      lb2s[t] = s2;
      ilbs[t] = __fdividef(1.0f, fmaxf(1.0f - s2, 1e-15f));
    } else if (t < 96){
      int ss = t - 32;
      const float* p = &enc_sh[ss*68];
      float q0=0.f,q1=0.f,q2=0.f,q3=0.f;
      #pragma unroll
      for (int i = 0; i < 64; i += 4){
        float4 v = *(const float4*)(p + i);
        q0 = fmaf(v.x, v.x, q0); q1 = fmaf(v.y, v.y, q1);
        q2 = fmaf(v.z, v.z, q2); q3 = fmaf(v.w, v.w, q3);
      }
      float s2 = (q0+q1)+(q2+q3);
      as2[ss] = s2;
      ias[ss] = __fdividef(1.0f, fmaxf(1.0f - s2, 1e-15f));
    }
    __syncthreads();

    float acc[4][2] = {{0.f,0.f},{0.f,0.f},{0.f,0.f},{0.f,0.f}};
    const float* lp = &lab_sh[li*68];
    const float* ep = &enc_sh[si*68];
    #pragma unroll
    for (int d4 = 0; d4 < 16; d4++){
      float4 la0 = *(const float4*)(lp + 4*d4);
      float4 la1 = *(const float4*)(lp + 8*68  + 4*d4);
      float4 la2 = *(const float4*)(lp + 16*68 + 4*d4);
      float4 la3 = *(const float4*)(lp + 24*68 + 4*d4);
      float4 e0  = *(const float4*)(ep + 4*d4);
      float4 e1  = *(const float4*)(ep + 32*68 + 4*d4);
      acc[0][0] = fmaf(la0.x,e0.x,fmaf(la0.y,e0.y,fmaf(la0.z,e0.z,fmaf(la0.w,e0.w,acc[0][0]))));
      acc[1][0] = fmaf(la1.x,e0.x,fmaf(la1.y,e0.y,fmaf(la1.z,e0.z,fmaf(la1.w,e0.w,acc[1][0]))));
      acc[2][0] = fmaf(la2.x,e0.x,fmaf(la2.y,e0.y,fmaf(la2.z,e0.z,fmaf(la2.w,e0.w,acc[2][0]))));
      acc[3][0] = fmaf(la3.x,e0.x,fmaf(la3.y,e0.y,fmaf(la3.z,e0.z,fmaf(la3.w,e0.w,acc[3][0]))));
      acc[0][1] = fmaf(la0.x,e1.x,fmaf(la0.y,e1.y,fmaf(la0.z,e1.z,fmaf(la0.w,e1.w,acc[0][1]))));
      acc[1][1] = fmaf(la1.x,e1.x,fmaf(la1.y,e1.y,fmaf(la1.z,e1.z,fmaf(la1.w,e1.w,acc[1][1]))));
      acc[2][1] = fmaf(la2.x,e1.x,fmaf(la2.y,e1.y,fmaf(la2.z,e1.z,fmaf(la2.w,e1.w,acc[2][1]))));
      acc[3][1] = fmaf(la3.x,e1.x,fmaf(la3.y,e1.y,fmaf(la3.z,e1.z,fmaf(la3.w,e1.w,acc[3][1]))));
    }
    #pragma unroll
    for (int a = 0; a < 4; a++){
      float lb2 = lb2s[li + a*8];
      float ilb = ilbs[li + a*8];
      #pragma unroll
      for (int q = 0; q < 2; q++){
        float av = as2[si + q*32];
        float ia = ias[si + q*32];
        float c2 = fmaxf(av + lb2 - 2.0f*acc[a][q], 0.0f);
        float tt = fmaxf(2.0f*c2*ia*ilb, 1e-7f);   // = arg - 1
        float prod = fmaf(tt, tt, 2.0f*tt);        // arg^2 - 1
        float sq;
        asm("sqrt.approx.f32 %0, %1;" : "=f"(sq) : "f"(prod));
        ds[a][q] += __logf(1.0f + tt + sq);        // arccosh(arg)
      }
    }
  }
  #pragma unroll
  for (int a = 0; a < 4; a++)
    #pragma unroll
    for (int q = 0; q < 2; q++)
      g_inter[(b*Ln + l0 + li + a*8)*Sn + s0 + si + q*32] = ds[a][q];
}

// ---------------- Kernel D: MLP  out[b,l] = w2 . relu(w1 @ inter + b1) + b2 ----------------
// GEMM [32768 x 256] * [256 x 128], 8x8 thread tile, k-major transposed A tile.
#define ATS 140
#define BTS 132
__global__ void kernelD(const float* __restrict__ w1, const float* __restrict__ b1,
                        const float* __restrict__ w2, const float* __restrict__ b2,
                        float* __restrict__ out){
  __shared__ float At[32*ATS];   // [k][row]
  __shared__ float Bs[32*BTS];   // [k][f]
  int t = threadIdx.x;
  int lane = t & 31;
  int cg = t & 15, rg = t >> 4;
  int r0 = blockIdx.x * 128;
  float acc[8][8];
  #pragma unroll
  for (int i = 0; i < 8; i++)
    #pragma unroll
    for (int j = 0; j < 8; j++) acc[i][j] = 0.f;

  for (int kc = 0; kc < 8; kc++){
    int s0 = kc * 32;
    #pragma unroll
    for (int it = 0; it < 16; it++){
      int row = (t >> 5) + it*8;
      At[lane*ATS + row] = g_inter[(r0 + row)*Sn + s0 + lane];
    }
    #pragma unroll
    for (int it = 0; it < 16; it++){
      int f = (t >> 5) + it*8;
      Bs[lane*BTS + f] = w1[f*Sn + s0 + lane];
    }
    __syncthreads();
    #pragma unroll
    for (int k = 0; k < 32; k++){
      float4 a0 = *(const float4*)(At + k*ATS + rg*8);
      float4 a1 = *(const float4*)(At + k*ATS + rg*8 + 4);
      float4 b0 = *(const float4*)(Bs + k*BTS + cg*8);
      float4 b1q = *(const float4*)(Bs + k*BTS + cg*8 + 4);
      float av[8] = {a0.x,a0.y,a0.z,a0.w,a1.x,a1.y,a1.z,a1.w};
      float bv[8] = {b0.x,b0.y,b0.z,b0.w,b1q.x,b1q.y,b1q.z,b1q.w};
      #pragma unroll
      for (int i = 0; i < 8; i++)
        #pragma unroll
        for (int j = 0; j < 8; j++)
          acc[i][j] = fmaf(av[i], bv[j], acc[i][j]);
    }
    __syncthreads();
  }
  float b1l[8], w2l[8];
  #pragma unroll
  for (int j = 0; j < 8; j++){
    int f = cg*8 + j;
    b1l[j] = b1[f];
    w2l[j] = w2[f];
  }
  float p[8];
  #pragma unroll
  for (int i = 0; i < 8; i++){
    float s = 0.f;
    #pragma unroll
    for (int j = 0; j < 8; j++)
      s = fmaf(fmaxf(acc[i][j] + b1l[j], 0.f), w2l[j], s);
    p[i] = s;
  }
  #pragma unroll
  for (int o = 1; o < 16; o <<= 1){
    #pragma unroll
    for (int i = 0; i < 8; i++) p[i] += __shfl_xor_sync(0xffffffffu, p[i], o);
  }
  if (cg == 0){
    float bb = b2[0];
    #pragma unroll
    for (int i = 0; i < 8; i++) out[r0 + rg*8 + i] = p[i] + bb;
  }
}

extern "C" void kernel_launch(void* const* d_in, const int* in_sizes, int n_in,
                              void* d_out, int out_size){
  const int*   x   = (const int*)  d_in[0];
  const float* we  = (const float*)d_in[1];
  const float* lab = (const float*)d_in[2];
  const float* W   = (const float*)d_in[3];
  const float* U   = (const float*)d_in[4];
  const float* bv  = (const float*)d_in[5];
  const float* w1  = (const float*)d_in[6];
  const float* b1  = (const float*)d_in[7];
  const float* w2  = (const float*)d_in[8];
  const float* b2  = (const float*)d_in[9];
  float* out = (float*)d_out;

  kernelA<<<1024, 32>>>(x, we, U, bv);
  kernelNop1<<<1, 32>>>();
  kernelNop2<<<1, 32>>>();
  kernelB<<<128, 32>>>(W, bv);       // 4th launch -> profiler target
  kernelC<<<4096, 256>>>(lab);
  kernelD<<<256, 256>>>(w1, b1, w2, b2, out);
}